// round 6
// baseline (speedup 1.0000x reference)
#include <cuda_runtime.h>
#include <cuda_bf16.h>
#include <math.h>

#define GN 8192
#define GF 512

// ---------------- device scratch (allocation-free) ----------------
__device__ __align__(16) float g_h [GN * GF];   // h = inp@W1+b1, fp32 [j][f]
__device__ __align__(16) float g_ht[GF * GN];   // h transposed, tf32-rounded [f][j]
__device__ float g_s1[GN], g_s2[GN];
__device__ float g_E1[GN], g_F1[GN], g_E2[GN], g_F2[GN];

// ---------------------------------------------------------------------------
// Kernel 1: h = inp @ W1 + b1 (fp32 SGEMM 128x128x8) + fused tf32 transpose
// epilogue: writes g_h [j][f] and g_ht [f][j] (tf32-rounded) in one pass.
// ---------------------------------------------------------------------------
__global__ __launch_bounds__(256) void gemm_h_kernel(
    const float* __restrict__ A,    // inp [8192][512]
    const float* __restrict__ B,    // W1  [512][512]
    const float* __restrict__ bias) // b1  [512]
{
    __shared__ float As[8][132];
    __shared__ float Bs[8][128];

    const int tid = threadIdx.x;
    const int bx = blockIdx.x;
    const int by = blockIdx.y;
    const int tx = tid & 15;
    const int ty = tid >> 4;

    float acc[8][8];
#pragma unroll
    for (int i = 0; i < 8; i++)
#pragma unroll
        for (int j = 0; j < 8; j++) acc[i][j] = 0.f;

    const int a_r = tid >> 1;
    const int a_k = (tid & 1) * 4;
    const int b_k = tid >> 5;
    const int b_n = (tid & 31) * 4;

    const float* Aptr = A + (by * 128 + a_r) * GF + a_k;
    const float* Bptr = B + b_k * GF + bx * 128 + b_n;

    for (int k0 = 0; k0 < GF; k0 += 8) {
        float4 av = *(const float4*)(Aptr + k0);
        float4 bv = *(const float4*)(Bptr + k0 * GF);
        __syncthreads();
        As[a_k + 0][a_r] = av.x;
        As[a_k + 1][a_r] = av.y;
        As[a_k + 2][a_r] = av.z;
        As[a_k + 3][a_r] = av.w;
        *(float4*)&Bs[b_k][b_n] = bv;
        __syncthreads();

#pragma unroll
        for (int kk = 0; kk < 8; kk++) {
            float af[8], bf[8];
#pragma unroll
            for (int i = 0; i < 8; i++) af[i] = As[kk][ty * 8 + i];
#pragma unroll
            for (int j = 0; j < 8; j++) bf[j] = Bs[kk][tx * 8 + j];
#pragma unroll
            for (int i = 0; i < 8; i++)
#pragma unroll
                for (int j = 0; j < 8; j++) acc[i][j] += af[i] * bf[j];
        }
    }

    const int row0 = by * 128 + ty * 8;
    const int col0 = bx * 128 + tx * 8;
    float4 bb0 = *(const float4*)(bias + col0);
    float4 bb1 = *(const float4*)(bias + col0 + 4);
#pragma unroll
    for (int i = 0; i < 8; i++) {
        acc[i][0] += bb0.x; acc[i][1] += bb0.y;
        acc[i][2] += bb0.z; acc[i][3] += bb0.w;
        acc[i][4] += bb1.x; acc[i][5] += bb1.y;
        acc[i][6] += bb1.z; acc[i][7] += bb1.w;
    }

    // normal-layout store (fp32, exact — used by s1s2 for the softmax factors)
#pragma unroll
    for (int i = 0; i < 8; i++) {
        float4 v0 = make_float4(acc[i][0], acc[i][1], acc[i][2], acc[i][3]);
        float4 v1 = make_float4(acc[i][4], acc[i][5], acc[i][6], acc[i][7]);
        *(float4*)&g_h[(row0 + i) * GF + col0]     = v0;
        *(float4*)&g_h[(row0 + i) * GF + col0 + 4] = v1;
    }

    // transposed tf32-rounded store (MMA B operand)
#pragma unroll
    for (int j = 0; j < 8; j++) {
        float t[8];
#pragma unroll
        for (int i = 0; i < 8; i++) {
            unsigned u;
            asm("cvt.rna.tf32.f32 %0, %1;" : "=r"(u) : "f"(acc[i][j]));
            t[i] = __uint_as_float(u);
        }
        float* dst = g_ht + (col0 + j) * GN + row0;
        *(float4*)dst       = make_float4(t[0], t[1], t[2], t[3]);
        *(float4*)(dst + 4) = make_float4(t[4], t[5], t[6], t[7]);
    }
}

// ---------------------------------------------------------------------------
// Kernel 2: s1[i] = h[i]·a1, s2[i] = h[i]·a2
// ---------------------------------------------------------------------------
__global__ __launch_bounds__(128) void s1s2_kernel(
    const float* __restrict__ a1, const float* __restrict__ a2)
{
    const int row = blockIdx.x;
    const int tid = threadIdx.x;

    float4 hv = *(const float4*)(g_h + row * GF + tid * 4);
    float4 v1 = *(const float4*)(a1 + tid * 4);
    float4 v2 = *(const float4*)(a2 + tid * 4);
    float p1 = hv.x * v1.x + hv.y * v1.y + hv.z * v1.z + hv.w * v1.w;
    float p2 = hv.x * v2.x + hv.y * v2.y + hv.z * v2.z + hv.w * v2.w;

#pragma unroll
    for (int o = 16; o > 0; o >>= 1) {
        p1 += __shfl_down_sync(0xffffffffu, p1, o);
        p2 += __shfl_down_sync(0xffffffffu, p2, o);
    }
    __shared__ float r1[4], r2[4];
    const int lane = tid & 31, w = tid >> 5;
    if (lane == 0) { r1[w] = p1; r2[w] = p2; }
    __syncthreads();
    if (tid == 0) {
        g_s1[row] = r1[0] + r1[1] + r1[2] + r1[3];
        g_s2[row] = r2[0] + r2[1] + r2[2] + r2[3];
    }
}

// ---------------------------------------------------------------------------
// Kernel 3: factorized exp.  x = s1_i + s2_j + b2.
//   exp(leaky(x)) = (x>0) ? E1_i*E2_j : F1_i*F2_j,  x>0 <=> E1_i*E2_j > 1
// ---------------------------------------------------------------------------
__global__ __launch_bounds__(256) void prep_kernel(const float* __restrict__ b2p)
{
    const int i = blockIdx.x * 256 + threadIdx.x;
    const float b2 = *b2p;
    const float x1 = g_s1[i] + b2;
    const float x2 = g_s2[i];
    g_E1[i] = __expf(x1);
    g_F1[i] = __expf(0.2f * x1);
    g_E2[i] = __expf(x2);
    g_F2[i] = __expf(0.2f * x2);
}

// ---------------------------------------------------------------------------
// Kernel 4: fused masked-softmax attention + attn@h + elu, tf32 mma.sync.
// 64 rows/CTA, 512 threads (16 warps, warp w owns cols [w*32, w*32+32)),
// j-tiles of 32, hT tile [512][32] double-buffered via cp.async.
// ---------------------------------------------------------------------------
#define AM 64
#define AK 32
#define NT (GN / AK)                             // 256 tiles
#define HTS 36                                   // padded f32 stride
#define HT_BYTES (GF * HTS * 4)                  // 73728
#define P_BYTES  (AM * HTS * 4)                  // 9216
#define SMEM_TOT (2 * HT_BYTES + P_BYTES + 3 * AM * 4)  // 157440

__global__ __launch_bounds__(512, 1) void gat_attn_mma(
    const int* __restrict__ adj,
    float* __restrict__ out)
{
    extern __shared__ char smraw[];
    float* hT0 = (float*)smraw;
    float* hT1 = (float*)(smraw + HT_BYTES);
    float* Ps  = (float*)(smraw + 2 * HT_BYTES);
    float* E1s = (float*)(smraw + 2 * HT_BYTES + P_BYTES);
    float* F1s = E1s + AM;
    float* ls  = E1s + 2 * AM;

    const int tid  = threadIdx.x;
    const int w    = tid >> 5;                   // warp 0..15
    const int lane = tid & 31;
    const int gid  = lane >> 2;                  // 0..7
    const int tig  = lane & 3;                   // 0..3
    const int i0   = blockIdx.x * AM;

    if (tid < AM) { E1s[tid] = g_E1[i0 + tid]; F1s[tid] = g_F1[i0 + tid]; }

    float acc[4][4][4];
#pragma unroll
    for (int mt = 0; mt < 4; mt++)
#pragma unroll
        for (int nt = 0; nt < 4; nt++)
#pragma unroll
            for (int q = 0; q < 4; q++) acc[mt][nt][q] = 0.f;

    // score mapping: thread -> row sr (0..63), cols sc+{0,8,16,24}
    const int sr = tid >> 3;
    const int sc = tid & 7;
    const long adjbase = (long)(i0 + sr) * GN;
    float lacc = 0.f;
    int am4[4];
#pragma unroll
    for (int q = 0; q < 4; q++)
        am4[q] = adj[adjbase + sc + q * 8];      // prefetch tile 0

    // cp.async per-thread mapping: 8 chunks of 16B; f = f0 + 64*s, part fixed
    const int f0   = tid >> 3;
    const int part = tid & 7;
    const float* srcbase = g_ht + (long)f0 * GN + part * 4;
    const unsigned dst0 = (unsigned)__cvta_generic_to_shared(hT0)
                        + (unsigned)(f0 * HTS + part * 4) * 4u;
    const unsigned dst1 = (unsigned)__cvta_generic_to_shared(hT1)
                        + (unsigned)(f0 * HTS + part * 4) * 4u;

    // prologue: load tile 0 into buf0
#pragma unroll
    for (int s = 0; s < 8; s++) {
        asm volatile("cp.async.ca.shared.global [%0], [%1], 16;\n"
                     :: "r"(dst0 + s * 64u * HTS * 4u),
                        "l"(srcbase + (long)s * 64 * GN));
    }
    asm volatile("cp.async.commit_group;\n");

    for (int t = 0; t < NT; t++) {
        const int j0 = t * AK;
        const unsigned dcur = (t & 1) ? dst1 : dst0;
        const unsigned dnxt = (t & 1) ? dst0 : dst1;
        const float* htb = (t & 1) ? hT1 : hT0;

        __syncthreads();   // prev MMA done: safe to overwrite P and buf[nxt]

        if (t + 1 < NT) {
#pragma unroll
            for (int s = 0; s < 8; s++) {
                asm volatile("cp.async.ca.shared.global [%0], [%1], 16;\n"
                             :: "r"(dnxt + s * 64u * HTS * 4u),
                                "l"(srcbase + (long)s * 64 * GN + j0 + AK));
            }
            asm volatile("cp.async.commit_group;\n");
        }

        // ---- scores (factorized exp, zero MUFU)
        {
            const float e1 = E1s[sr];
            const float f1 = F1s[sr];
#pragma unroll
            for (int q = 0; q < 4; q++) {
                const int c = sc + q * 8;
                const float u  = e1 * g_E2[j0 + c];
                const float vv = f1 * g_F2[j0 + c];
                float p = (am4[q] > 0) ? (u > 1.f ? u : vv) : 0.f;
                unsigned pt;
                asm("cvt.rna.tf32.f32 %0, %1;" : "=r"(pt) : "f"(p));
                const float pr = __uint_as_float(pt);
                lacc += pr;
                Ps[sr * HTS + c] = pr;
            }
        }

        // ---- prefetch adj for next tile
        if (t + 1 < NT) {
#pragma unroll
            for (int q = 0; q < 4; q++)
                am4[q] = adj[adjbase + j0 + AK + sc + q * 8];
        }

        if (t + 1 < NT)
            asm volatile("cp.async.wait_group 1;\n" ::: "memory");
        else
            asm volatile("cp.async.wait_group 0;\n" ::: "memory");
        __syncthreads();                           // hT[cur] + Ps ready

        // ---- MAC: 4 k-steps of m16n8k8 tf32, 16 MMAs each
#pragma unroll
        for (int ks = 0; ks < 4; ks++) {
            const int k0 = ks * 8;
            unsigned a[4][4];
#pragma unroll
            for (int mt = 0; mt < 4; mt++) {
                const float* ap = Ps + (mt * 16 + gid) * HTS + k0 + tig;
                a[mt][0] = __float_as_uint(ap[0]);
                a[mt][1] = __float_as_uint(ap[8 * HTS]);
                a[mt][2] = __float_as_uint(ap[4]);
                a[mt][3] = __float_as_uint(ap[8 * HTS + 4]);
            }
#pragma unroll
            for (int nt = 0; nt < 4; nt++) {
                const float* bp = htb + (w * 32 + nt * 8 + gid) * HTS + k0 + tig;
                const unsigned b0 = __float_as_uint(bp[0]);
                const unsigned b1 = __float_as_uint(bp[4]);
#pragma unroll
                for (int mt = 0; mt < 4; mt++) {
                    asm volatile(
                        "mma.sync.aligned.m16n8k8.row.col.f32.tf32.tf32.f32 "
                        "{%0,%1,%2,%3}, {%4,%5,%6,%7}, {%8,%9}, {%0,%1,%2,%3};\n"
                        : "+f"(acc[mt][nt][0]), "+f"(acc[mt][nt][1]),
                          "+f"(acc[mt][nt][2]), "+f"(acc[mt][nt][3])
                        : "r"(a[mt][0]), "r"(a[mt][1]),
                          "r"(a[mt][2]), "r"(a[mt][3]),
                          "r"(b0), "r"(b1));
                }
            }
        }
    }

    // ---- row sums: 8 threads per row (consecutive lanes), shfl width 8
    {
        float v = lacc;
        v += __shfl_down_sync(0xffffffffu, v, 4, 8);
        v += __shfl_down_sync(0xffffffffu, v, 2, 8);
        v += __shfl_down_sync(0xffffffffu, v, 1, 8);
        if (sc == 0) ls[sr] = v;
    }
    __syncthreads();

    // ---- epilogue: normalize + elu + store
#pragma unroll
    for (int mt = 0; mt < 4; mt++) {
        const int r1 = mt * 16 + gid;
        const int r2 = r1 + 8;
        const float inv1 = 1.0f / ls[r1];
        const float inv2 = 1.0f / ls[r2];
#pragma unroll
        for (int nt = 0; nt < 4; nt++) {
            const int col = w * 32 + nt * 8 + tig * 2;
            float o0 = acc[mt][nt][0] * inv1;
            float o1 = acc[mt][nt][1] * inv1;
            float o2 = acc[mt][nt][2] * inv2;
            float o3 = acc[mt][nt][3] * inv2;
            o0 = o0 > 0.f ? o0 : (__expf(o0) - 1.f);
            o1 = o1 > 0.f ? o1 : (__expf(o1) - 1.f);
            o2 = o2 > 0.f ? o2 : (__expf(o2) - 1.f);
            o3 = o3 > 0.f ? o3 : (__expf(o3) - 1.f);
            *(float2*)&out[(i0 + r1) * GF + col] = make_float2(o0, o1);
            *(float2*)&out[(i0 + r2) * GF + col] = make_float2(o2, o3);
        }
    }
}

// ---------------------------------------------------------------------------
extern "C" void kernel_launch(void* const* d_in, const int* in_sizes, int n_in,
                              void* d_out, int out_size)
{
    const float* inp = (const float*)d_in[0];
    const int*   adj = (const int*)d_in[1];
    const float* W1  = (const float*)d_in[2];
    const float* b1  = (const float*)d_in[3];
    const float* a1  = (const float*)d_in[4];
    const float* a2  = (const float*)d_in[5];
    const float* b2  = (const float*)d_in[6];
    float* out = (float*)d_out;

    (void)in_sizes; (void)n_in; (void)out_size;

    cudaFuncSetAttribute(gat_attn_mma,
                         cudaFuncAttributeMaxDynamicSharedMemorySize, SMEM_TOT);

    gemm_h_kernel<<<dim3(GF / 128, GN / 128), 256>>>(inp, W1, b1);
    s1s2_kernel<<<GN, 128>>>(a1, a2);
    prep_kernel<<<GN / 256, 256>>>(b2);
    gat_attn_mma<<<GN / AM, 512, SMEM_TOT>>>(adj, out);
}

// round 7
// speedup vs baseline: 1.0002x; 1.0002x over previous
#include <cuda_runtime.h>
#include <cuda_bf16.h>
#include <math.h>

#define GN 8192
#define GF 512

// ---------------- device scratch (allocation-free) ----------------
__device__ __align__(16) float g_h [GN * GF];   // h = inp@W1+b1, fp32 [j][f]
__device__ __align__(16) float g_ht[GF * GN];   // h transposed, tf32-rounded [f][j]
__device__ float g_s1[GN], g_s2[GN];
__device__ float g_E1[GN], g_F1[GN], g_E2[GN], g_F2[GN];

// ---------------------------------------------------------------------------
// Kernel 1: h = inp @ W1 + b1 (fp32 SGEMM 128x128x8) + fused tf32 transpose
// epilogue: writes g_h [j][f] and g_ht [f][j] (tf32-rounded) in one pass.
// ---------------------------------------------------------------------------
__global__ __launch_bounds__(256) void gemm_h_kernel(
    const float* __restrict__ A,    // inp [8192][512]
    const float* __restrict__ B,    // W1  [512][512]
    const float* __restrict__ bias) // b1  [512]
{
    __shared__ float As[8][132];
    __shared__ float Bs[8][128];

    const int tid = threadIdx.x;
    const int bx = blockIdx.x;
    const int by = blockIdx.y;
    const int tx = tid & 15;
    const int ty = tid >> 4;

    float acc[8][8];
#pragma unroll
    for (int i = 0; i < 8; i++)
#pragma unroll
        for (int j = 0; j < 8; j++) acc[i][j] = 0.f;

    const int a_r = tid >> 1;
    const int a_k = (tid & 1) * 4;
    const int b_k = tid >> 5;
    const int b_n = (tid & 31) * 4;

    const float* Aptr = A + (by * 128 + a_r) * GF + a_k;
    const float* Bptr = B + b_k * GF + bx * 128 + b_n;

    for (int k0 = 0; k0 < GF; k0 += 8) {
        float4 av = *(const float4*)(Aptr + k0);
        float4 bv = *(const float4*)(Bptr + k0 * GF);
        __syncthreads();
        As[a_k + 0][a_r] = av.x;
        As[a_k + 1][a_r] = av.y;
        As[a_k + 2][a_r] = av.z;
        As[a_k + 3][a_r] = av.w;
        *(float4*)&Bs[b_k][b_n] = bv;
        __syncthreads();

#pragma unroll
        for (int kk = 0; kk < 8; kk++) {
            float af[8], bf[8];
#pragma unroll
            for (int i = 0; i < 8; i++) af[i] = As[kk][ty * 8 + i];
#pragma unroll
            for (int j = 0; j < 8; j++) bf[j] = Bs[kk][tx * 8 + j];
#pragma unroll
            for (int i = 0; i < 8; i++)
#pragma unroll
                for (int j = 0; j < 8; j++) acc[i][j] += af[i] * bf[j];
        }
    }

    const int row0 = by * 128 + ty * 8;
    const int col0 = bx * 128 + tx * 8;
    float4 bb0 = *(const float4*)(bias + col0);
    float4 bb1 = *(const float4*)(bias + col0 + 4);
#pragma unroll
    for (int i = 0; i < 8; i++) {
        acc[i][0] += bb0.x; acc[i][1] += bb0.y;
        acc[i][2] += bb0.z; acc[i][3] += bb0.w;
        acc[i][4] += bb1.x; acc[i][5] += bb1.y;
        acc[i][6] += bb1.z; acc[i][7] += bb1.w;
    }

    // normal-layout store (fp32, exact — used by s1s2 for the softmax factors)
#pragma unroll
    for (int i = 0; i < 8; i++) {
        float4 v0 = make_float4(acc[i][0], acc[i][1], acc[i][2], acc[i][3]);
        float4 v1 = make_float4(acc[i][4], acc[i][5], acc[i][6], acc[i][7]);
        *(float4*)&g_h[(row0 + i) * GF + col0]     = v0;
        *(float4*)&g_h[(row0 + i) * GF + col0 + 4] = v1;
    }

    // transposed tf32-rounded store (MMA B operand)
#pragma unroll
    for (int j = 0; j < 8; j++) {
        float t[8];
#pragma unroll
        for (int i = 0; i < 8; i++) {
            unsigned u;
            asm("cvt.rna.tf32.f32 %0, %1;" : "=r"(u) : "f"(acc[i][j]));
            t[i] = __uint_as_float(u);
        }
        float* dst = g_ht + (col0 + j) * GN + row0;
        *(float4*)dst       = make_float4(t[0], t[1], t[2], t[3]);
        *(float4*)(dst + 4) = make_float4(t[4], t[5], t[6], t[7]);
    }
}

// ---------------------------------------------------------------------------
// Kernel 2: s1[i] = h[i]·a1, s2[i] = h[i]·a2
// ---------------------------------------------------------------------------
__global__ __launch_bounds__(128) void s1s2_kernel(
    const float* __restrict__ a1, const float* __restrict__ a2)
{
    const int row = blockIdx.x;
    const int tid = threadIdx.x;

    float4 hv = *(const float4*)(g_h + row * GF + tid * 4);
    float4 v1 = *(const float4*)(a1 + tid * 4);
    float4 v2 = *(const float4*)(a2 + tid * 4);
    float p1 = hv.x * v1.x + hv.y * v1.y + hv.z * v1.z + hv.w * v1.w;
    float p2 = hv.x * v2.x + hv.y * v2.y + hv.z * v2.z + hv.w * v2.w;

#pragma unroll
    for (int o = 16; o > 0; o >>= 1) {
        p1 += __shfl_down_sync(0xffffffffu, p1, o);
        p2 += __shfl_down_sync(0xffffffffu, p2, o);
    }
    __shared__ float r1[4], r2[4];
    const int lane = tid & 31, w = tid >> 5;
    if (lane == 0) { r1[w] = p1; r2[w] = p2; }
    __syncthreads();
    if (tid == 0) {
        g_s1[row] = r1[0] + r1[1] + r1[2] + r1[3];
        g_s2[row] = r2[0] + r2[1] + r2[2] + r2[3];
    }
}

// ---------------------------------------------------------------------------
// Kernel 3: factorized exp.  x = s1_i + s2_j + b2.
//   exp(leaky(x)) = (x>0) ? E1_i*E2_j : F1_i*F2_j,  x>0 <=> E1_i*E2_j > 1
// ---------------------------------------------------------------------------
__global__ __launch_bounds__(256) void prep_kernel(const float* __restrict__ b2p)
{
    const int i = blockIdx.x * 256 + threadIdx.x;
    const float b2 = *b2p;
    const float x1 = g_s1[i] + b2;
    const float x2 = g_s2[i];
    g_E1[i] = __expf(x1);
    g_F1[i] = __expf(0.2f * x1);
    g_E2[i] = __expf(x2);
    g_F2[i] = __expf(0.2f * x2);
}

// ---------------------------------------------------------------------------
// Kernel 4: fused masked-softmax attention + attn@h + elu, tf32 mma.sync.
// 64 rows/CTA, 512 threads (16 warps, warp w owns cols [w*32, w*32+32)),
// j-tiles of 32, hT tile [512][32] double-buffered via cp.async.
// ---------------------------------------------------------------------------
#define AM 64
#define AK 32
#define NT (GN / AK)                             // 256 tiles
#define HTS 36                                   // padded f32 stride
#define HT_BYTES (GF * HTS * 4)                  // 73728
#define P_BYTES  (AM * HTS * 4)                  // 9216
#define SMEM_TOT (2 * HT_BYTES + P_BYTES + 3 * AM * 4)  // 157440

__global__ __launch_bounds__(512, 1) void gat_attn_mma(
    const int* __restrict__ adj,
    float* __restrict__ out)
{
    extern __shared__ char smraw[];
    float* hT0 = (float*)smraw;
    float* hT1 = (float*)(smraw + HT_BYTES);
    float* Ps  = (float*)(smraw + 2 * HT_BYTES);
    float* E1s = (float*)(smraw + 2 * HT_BYTES + P_BYTES);
    float* F1s = E1s + AM;
    float* ls  = E1s + 2 * AM;

    const int tid  = threadIdx.x;
    const int w    = tid >> 5;                   // warp 0..15
    const int lane = tid & 31;
    const int gid  = lane >> 2;                  // 0..7
    const int tig  = lane & 3;                   // 0..3
    const int i0   = blockIdx.x * AM;

    if (tid < AM) { E1s[tid] = g_E1[i0 + tid]; F1s[tid] = g_F1[i0 + tid]; }

    float acc[4][4][4];
#pragma unroll
    for (int mt = 0; mt < 4; mt++)
#pragma unroll
        for (int nt = 0; nt < 4; nt++)
#pragma unroll
            for (int q = 0; q < 4; q++) acc[mt][nt][q] = 0.f;

    // score mapping: thread -> row sr (0..63), cols sc+{0,8,16,24}
    const int sr = tid >> 3;
    const int sc = tid & 7;
    const long adjbase = (long)(i0 + sr) * GN;
    float lacc = 0.f;
    int am4[4];
#pragma unroll
    for (int q = 0; q < 4; q++)
        am4[q] = adj[adjbase + sc + q * 8];      // prefetch tile 0

    // cp.async per-thread mapping: 8 chunks of 16B; f = f0 + 64*s, part fixed
    const int f0   = tid >> 3;
    const int part = tid & 7;
    const float* srcbase = g_ht + (long)f0 * GN + part * 4;
    const unsigned dst0 = (unsigned)__cvta_generic_to_shared(hT0)
                        + (unsigned)(f0 * HTS + part * 4) * 4u;
    const unsigned dst1 = (unsigned)__cvta_generic_to_shared(hT1)
                        + (unsigned)(f0 * HTS + part * 4) * 4u;

    // prologue: load tile 0 into buf0
#pragma unroll
    for (int s = 0; s < 8; s++) {
        asm volatile("cp.async.ca.shared.global [%0], [%1], 16;\n"
                     :: "r"(dst0 + s * 64u * HTS * 4u),
                        "l"(srcbase + (long)s * 64 * GN));
    }
    asm volatile("cp.async.commit_group;\n");

    for (int t = 0; t < NT; t++) {
        const int j0 = t * AK;
        const unsigned dcur = (t & 1) ? dst1 : dst0;
        const unsigned dnxt = (t & 1) ? dst0 : dst1;
        const float* htb = (t & 1) ? hT1 : hT0;

        __syncthreads();   // prev MMA done: safe to overwrite P and buf[nxt]

        if (t + 1 < NT) {
#pragma unroll
            for (int s = 0; s < 8; s++) {
                asm volatile("cp.async.ca.shared.global [%0], [%1], 16;\n"
                             :: "r"(dnxt + s * 64u * HTS * 4u),
                                "l"(srcbase + (long)s * 64 * GN + j0 + AK));
            }
            asm volatile("cp.async.commit_group;\n");
        }

        // ---- scores (factorized exp, zero MUFU)
        {
            const float e1 = E1s[sr];
            const float f1 = F1s[sr];
#pragma unroll
            for (int q = 0; q < 4; q++) {
                const int c = sc + q * 8;
                const float u  = e1 * g_E2[j0 + c];
                const float vv = f1 * g_F2[j0 + c];
                float p = (am4[q] > 0) ? (u > 1.f ? u : vv) : 0.f;
                unsigned pt;
                asm("cvt.rna.tf32.f32 %0, %1;" : "=r"(pt) : "f"(p));
                const float pr = __uint_as_float(pt);
                lacc += pr;
                Ps[sr * HTS + c] = pr;
            }
        }

        // ---- prefetch adj for next tile
        if (t + 1 < NT) {
#pragma unroll
            for (int q = 0; q < 4; q++)
                am4[q] = adj[adjbase + j0 + AK + sc + q * 8];
        }

        if (t + 1 < NT)
            asm volatile("cp.async.wait_group 1;\n" ::: "memory");
        else
            asm volatile("cp.async.wait_group 0;\n" ::: "memory");
        __syncthreads();                           // hT[cur] + Ps ready

        // ---- MAC: 4 k-steps of m16n8k8 tf32, 16 MMAs each
#pragma unroll
        for (int ks = 0; ks < 4; ks++) {
            const int k0 = ks * 8;
            unsigned a[4][4];
#pragma unroll
            for (int mt = 0; mt < 4; mt++) {
                const float* ap = Ps + (mt * 16 + gid) * HTS + k0 + tig;
                a[mt][0] = __float_as_uint(ap[0]);
                a[mt][1] = __float_as_uint(ap[8 * HTS]);
                a[mt][2] = __float_as_uint(ap[4]);
                a[mt][3] = __float_as_uint(ap[8 * HTS + 4]);
            }
#pragma unroll
            for (int nt = 0; nt < 4; nt++) {
                const float* bp = htb + (w * 32 + nt * 8 + gid) * HTS + k0 + tig;
                const unsigned b0 = __float_as_uint(bp[0]);
                const unsigned b1 = __float_as_uint(bp[4]);
#pragma unroll
                for (int mt = 0; mt < 4; mt++) {
                    asm volatile(
                        "mma.sync.aligned.m16n8k8.row.col.f32.tf32.tf32.f32 "
                        "{%0,%1,%2,%3}, {%4,%5,%6,%7}, {%8,%9}, {%0,%1,%2,%3};\n"
                        : "+f"(acc[mt][nt][0]), "+f"(acc[mt][nt][1]),
                          "+f"(acc[mt][nt][2]), "+f"(acc[mt][nt][3])
                        : "r"(a[mt][0]), "r"(a[mt][1]),
                          "r"(a[mt][2]), "r"(a[mt][3]),
                          "r"(b0), "r"(b1));
                }
            }
        }
    }

    // ---- row sums: 8 threads per row (consecutive lanes), shfl width 8
    {
        float v = lacc;
        v += __shfl_down_sync(0xffffffffu, v, 4, 8);
        v += __shfl_down_sync(0xffffffffu, v, 2, 8);
        v += __shfl_down_sync(0xffffffffu, v, 1, 8);
        if (sc == 0) ls[sr] = v;
    }
    __syncthreads();

    // ---- epilogue: normalize + elu + store
#pragma unroll
    for (int mt = 0; mt < 4; mt++) {
        const int r1 = mt * 16 + gid;
        const int r2 = r1 + 8;
        const float inv1 = 1.0f / ls[r1];
        const float inv2 = 1.0f / ls[r2];
#pragma unroll
        for (int nt = 0; nt < 4; nt++) {
            const int col = w * 32 + nt * 8 + tig * 2;
            float o0 = acc[mt][nt][0] * inv1;
            float o1 = acc[mt][nt][1] * inv1;
            float o2 = acc[mt][nt][2] * inv2;
            float o3 = acc[mt][nt][3] * inv2;
            o0 = o0 > 0.f ? o0 : (__expf(o0) - 1.f);
            o1 = o1 > 0.f ? o1 : (__expf(o1) - 1.f);
            o2 = o2 > 0.f ? o2 : (__expf(o2) - 1.f);
            o3 = o3 > 0.f ? o3 : (__expf(o3) - 1.f);
            *(float2*)&out[(i0 + r1) * GF + col] = make_float2(o0, o1);
            *(float2*)&out[(i0 + r2) * GF + col] = make_float2(o2, o3);
        }
    }
}

// ---------------------------------------------------------------------------
extern "C" void kernel_launch(void* const* d_in, const int* in_sizes, int n_in,
                              void* d_out, int out_size)
{
    const float* inp = (const float*)d_in[0];
    const int*   adj = (const int*)d_in[1];
    const float* W1  = (const float*)d_in[2];
    const float* b1  = (const float*)d_in[3];
    const float* a1  = (const float*)d_in[4];
    const float* a2  = (const float*)d_in[5];
    const float* b2  = (const float*)d_in[6];
    float* out = (float*)d_out;

    (void)in_sizes; (void)n_in; (void)out_size;

    cudaFuncSetAttribute(gat_attn_mma,
                         cudaFuncAttributeMaxDynamicSharedMemorySize, SMEM_TOT);

    gemm_h_kernel<<<dim3(GF / 128, GN / 128), 256>>>(inp, W1, b1);
    s1s2_kernel<<<GN, 128>>>(a1, a2);
    prep_kernel<<<GN / 256, 256>>>(b2);
    gat_attn_mma<<<GN / AM, 512, SMEM_TOT>>>(adj, out);
}